// round 5
// baseline (speedup 1.0000x reference)
#include <cuda_runtime.h>
#include <cuda_bf16.h>
#include <cstdint>

// Problem constants
#define BB 64
#define UU 512
#define AE 1024
#define UE 256
#define AA 256           // head size / GEMM K for attention
#define MTOT (BB*UU)     // 32768 rows

// Q/K stored as bf16 hi/lo split pairs (x = hi + lo)
__device__ __nv_bfloat16 g_Qhi[(size_t)MTOT * AA];
__device__ __nv_bfloat16 g_Qlo[(size_t)MTOT * AA];
__device__ __nv_bfloat16 g_Khi[(size_t)MTOT * AA];
__device__ __nv_bfloat16 g_Klo[(size_t)MTOT * AA];

// ---------------------------------------------------------------------------
// Adaptive int width (JAX w/o x64 silently emits int32 despite astype(int64)).
// ---------------------------------------------------------------------------
__device__ __forceinline__ bool counts_are_64bit(const int* p) {
    bool z = true;
    #pragma unroll
    for (int i = 1; i < 64; i += 2) z &= (p[i] == 0);
    return z;
}
__device__ __forceinline__ int load_count(const int* p, int b, bool is64) {
    return is64 ? p[2 * b] : p[b];
}

// ---------------------------------------------------------------------------
// MMA / async helpers
// ---------------------------------------------------------------------------
__device__ __forceinline__ void ldmx4(uint32_t* r, const void* ptr) {
    uint32_t a = (uint32_t)__cvta_generic_to_shared(ptr);
    asm volatile("ldmatrix.sync.aligned.m8n8.x4.shared.b16 {%0,%1,%2,%3}, [%4];"
                 : "=r"(r[0]), "=r"(r[1]), "=r"(r[2]), "=r"(r[3]) : "r"(a));
}
__device__ __forceinline__ void mma_bf16(float* d, const uint32_t* a, uint32_t b0, uint32_t b1) {
    asm volatile("mma.sync.aligned.m16n8k16.row.col.f32.bf16.bf16.f32 "
                 "{%0,%1,%2,%3}, {%4,%5,%6,%7}, {%8,%9}, {%0,%1,%2,%3};"
                 : "+f"(d[0]), "+f"(d[1]), "+f"(d[2]), "+f"(d[3])
                 : "r"(a[0]), "r"(a[1]), "r"(a[2]), "r"(a[3]), "r"(b0), "r"(b1));
}
__device__ __forceinline__ void split_bf16(float v, __nv_bfloat16& h, __nv_bfloat16& l) {
    h = __float2bfloat16(v);
    l = __float2bfloat16(v - __bfloat162float(h));
}
__device__ __forceinline__ void cp16(void* dst, const void* src) {
    uint32_t d = (uint32_t)__cvta_generic_to_shared(dst);
    asm volatile("cp.async.cg.shared.global [%0], [%1], 16;" :: "r"(d), "l"(src));
}
__device__ __forceinline__ void cp_commit() {
    asm volatile("cp.async.commit_group;");
}
template<int N> __device__ __forceinline__ void cp_wait() {
    asm volatile("cp.async.wait_group %0;" :: "n"(N));
}

// ===========================================================================
// Projection GEMM, bf16 split-3, double-buffered smem:
//   C[M,256] = concat(A0|A1)[M,ktot] @ W[ktot,256] + bias -> bf16 hi/lo out
// ===========================================================================
#define BM 128
#define BN 64
#define BK 16
#define LDT (BK + 8)

__global__ void __launch_bounds__(256)
proj_split3(const float* __restrict__ A0, int lda0, int k0,
            const float* __restrict__ A1, int lda1, int ktot,
            const float* __restrict__ W, const float* __restrict__ bias,
            __nv_bfloat16* __restrict__ Chi, __nv_bfloat16* __restrict__ Clo)
{
    __shared__ __align__(16) __nv_bfloat16 Ah[2][BM][LDT], Al[2][BM][LDT];
    __shared__ __align__(16) __nv_bfloat16 Bh[2][BN][LDT], Bl[2][BN][LDT];

    const int tid  = threadIdx.x;
    const int warp = tid >> 5, lane = tid & 31;
    const int wr = (warp >> 1) * 32;
    const int wc = (warp & 1) * 32;
    const int row0 = blockIdx.y * BM;
    const int col0 = blockIdx.x * BN;

    const int arow = tid >> 1;
    const int ak   = (tid & 1) * 8;
    const int wk = tid & 15;
    const int wn = (tid >> 4) * 4;

    float acc[2][4][4] = {};
    float4 pa0, pa1, pw;

    auto loadA = [&](int kk) {
        const float* src; int lda, cb;
        if (kk < k0) { src = A0; lda = lda0; cb = kk; }
        else         { src = A1; lda = lda1; cb = kk - k0; }
        const float4* p = (const float4*)&src[(size_t)(row0 + arow) * lda + cb + ak];
        pa0 = p[0]; pa1 = p[1];
    };
    auto loadW = [&](int kk) {
        pw = *(const float4*)&W[(size_t)(kk + wk) * AA + col0 + wn];
    };
    auto stage = [&](int buf) {
        #pragma unroll
        for (int j = 0; j < 4; ++j) {
            __nv_bfloat16 h, l;
            split_bf16((&pa0.x)[j], h, l);
            Ah[buf][arow][ak + j] = h; Al[buf][arow][ak + j] = l;
            split_bf16((&pa1.x)[j], h, l);
            Ah[buf][arow][ak + 4 + j] = h; Al[buf][arow][ak + 4 + j] = l;
            split_bf16((&pw.x)[j], h, l);
            Bh[buf][wn + j][wk] = h; Bl[buf][wn + j][wk] = l;
        }
    };

    loadA(0); loadW(0);
    stage(0);
    __syncthreads();

    const int lrow = lane & 15;
    const int lcol = (lane >> 4) * 8;

    int it = 0;
    for (int kk = 0; kk < ktot; kk += BK, ++it) {
        const bool more = (kk + BK) < ktot;
        if (more) { loadA(kk + BK); loadW(kk + BK); }

        const int buf = it & 1;
        uint32_t ah[2][4], al2[2][4], bh[2][4], bl[2][4];
        #pragma unroll
        for (int mi = 0; mi < 2; ++mi) {
            ldmx4(ah[mi],  &Ah[buf][wr + mi * 16 + lrow][lcol]);
            ldmx4(al2[mi], &Al[buf][wr + mi * 16 + lrow][lcol]);
        }
        #pragma unroll
        for (int p = 0; p < 2; ++p) {
            ldmx4(bh[p], &Bh[buf][wc + p * 16 + lrow][lcol]);
            ldmx4(bl[p], &Bl[buf][wc + p * 16 + lrow][lcol]);
        }
        #pragma unroll
        for (int mi = 0; mi < 2; ++mi)
            #pragma unroll
            for (int p = 0; p < 2; ++p)
                #pragma unroll
                for (int t = 0; t < 2; ++t) {
                    float* d = acc[mi][p * 2 + t];
                    mma_bf16(d, ah[mi],  bh[p][t], bh[p][t + 2]);
                    mma_bf16(d, ah[mi],  bl[p][t], bl[p][t + 2]);
                    mma_bf16(d, al2[mi], bh[p][t], bh[p][t + 2]);
                }

        if (more) stage((it + 1) & 1);
        __syncthreads();
    }

    // epilogue: +bias, split to hi/lo, store
    #pragma unroll
    for (int mi = 0; mi < 2; ++mi)
        #pragma unroll
        for (int ni = 0; ni < 4; ++ni) {
            const int r = row0 + wr + mi * 16 + (lane >> 2);
            const int c = col0 + wc + ni * 8 + (lane & 3) * 2;
            const float b0 = bias[c], b1 = bias[c + 1];
            #pragma unroll
            for (int h = 0; h < 2; ++h) {
                const int row = r + h * 8;
                float v0 = acc[mi][ni][h * 2 + 0] + b0;
                float v1 = acc[mi][ni][h * 2 + 1] + b1;
                __nv_bfloat16 h0, l0, h1, l1;
                split_bf16(v0, h0, l0);
                split_bf16(v1, h1, l1);
                __nv_bfloat162 hh; hh.x = h0; hh.y = h1;
                __nv_bfloat162 ll; ll.x = l0; ll.y = l1;
                *(__nv_bfloat162*)&Chi[(size_t)row * AA + c] = hh;
                *(__nv_bfloat162*)&Clo[(size_t)row * AA + c] = ll;
            }
        }
}

// ===========================================================================
// Fused attention + softmax.
// Block = (batch b, 64 query rows). Q tile resident in smem (hi/lo).
// Loop 8 key-chunks of 64; per chunk GEMM 64x64xK256 via cp.async-pipelined
// K staging (32-k stages, 2-deep ring). Scores accumulate in padded smem.
// Then in-block masked softmax writes final output (single pass to HBM).
// ===========================================================================
#define LDQ (AA + 8)      // 264 bf16
#define BKA 32
#define LDB (BKA + 8)     // 40 bf16
#define LDS (UU + 8)      // 520 f32

#define Q_BYTES   (64 * LDQ * 2)            // 33792
#define BUF_BYTES (64 * LDB * 2)            // 5120
#define SM_QH 0
#define SM_QL (SM_QH + Q_BYTES)
#define SM_B0 (SM_QL + Q_BYTES)             // Bh0,Bl0,Bh1,Bl1
#define SM_S  (SM_B0 + 4 * BUF_BYTES)
#define SM_TOTAL (SM_S + 64 * LDS * 4)      // 221184

__global__ void __launch_bounds__(256)
attn_fused(const int* __restrict__ nr_own, const int* __restrict__ nr_enemy,
           const int* __restrict__ nr_flags, float* __restrict__ out)
{
    extern __shared__ __align__(16) char sm[];
    __nv_bfloat16* Qh = (__nv_bfloat16*)(sm + SM_QH);
    __nv_bfloat16* Ql = (__nv_bfloat16*)(sm + SM_QL);
    float* S = (float*)(sm + SM_S);

    const int tid  = threadIdx.x;
    const int warp = tid >> 5, lane = tid & 31;
    const int b    = blockIdx.y;
    const int row0 = blockIdx.x * 64;

    const __nv_bfloat16* gQh = g_Qhi + (size_t)b * UU * AA;
    const __nv_bfloat16* gQl = g_Qlo + (size_t)b * UU * AA;
    const __nv_bfloat16* gKh = g_Khi + (size_t)b * UU * AA;
    const __nv_bfloat16* gKl = g_Klo + (size_t)b * UU * AA;

    // ---- load Q tile (64 x 256 hi/lo) ----
    #pragma unroll
    for (int i = 0; i < 8; ++i) {
        int idx = tid + i * 256;         // 0..2047
        int r = idx >> 5;                // 64 rows
        int c = (idx & 31) * 8;          // 32 x 8 elems
        *(uint4*)&Qh[r * LDQ + c] = *(const uint4*)&gQh[(size_t)(row0 + r) * AA + c];
        *(uint4*)&Ql[r * LDQ + c] = *(const uint4*)&gQl[(size_t)(row0 + r) * AA + c];
    }

    // ---- K staging ring ----
    const int krow = tid >> 2;           // 0..63
    const int koff = (tid & 3) * 8;      // 8 bf16 = 16B
    auto prefetch = [&](int it) {
        const int kc = it >> 3, kk = (it & 7) * BKA, buf = it & 1;
        __nv_bfloat16* dh = (__nv_bfloat16*)(sm + SM_B0 + (2 * buf + 0) * BUF_BYTES);
        __nv_bfloat16* dl = (__nv_bfloat16*)(sm + SM_B0 + (2 * buf + 1) * BUF_BYTES);
        const size_t g = (size_t)(kc * 64 + krow) * AA + kk + koff;
        cp16(&dh[krow * LDB + koff], &gKh[g]);
        cp16(&dl[krow * LDB + koff], &gKl[g]);
        cp_commit();
    };

    prefetch(0);
    __syncthreads();   // Q visible (cp.async pending is fine)

    const int wq = (warp & 3) * 16;      // query rows of warp
    const int wk = (warp >> 2) * 32;     // keys (chunk-relative)
    const int lrow = lane & 15;
    const int lcol = (lane >> 4) * 8;

    float acc[4][4] = {};

    for (int it = 0; it < 64; ++it) {
        const bool more = it < 63;
        if (more) prefetch(it + 1);
        if (more) cp_wait<1>(); else cp_wait<0>();
        __syncthreads();

        const int kc = it >> 3, kk = (it & 7) * BKA, buf = it & 1;
        const __nv_bfloat16* Bhb = (const __nv_bfloat16*)(sm + SM_B0 + (2 * buf + 0) * BUF_BYTES);
        const __nv_bfloat16* Blb = (const __nv_bfloat16*)(sm + SM_B0 + (2 * buf + 1) * BUF_BYTES);

        uint32_t ah[2][4], al2[2][4], bh[2][2][4], bl[2][2][4];
        #pragma unroll
        for (int h = 0; h < 2; ++h) {
            ldmx4(ah[h],  &Qh[(wq + lrow) * LDQ + kk + h * 16 + lcol]);
            ldmx4(al2[h], &Ql[(wq + lrow) * LDQ + kk + h * 16 + lcol]);
        }
        #pragma unroll
        for (int p = 0; p < 2; ++p)
            #pragma unroll
            for (int h = 0; h < 2; ++h) {
                ldmx4(bh[p][h], &Bhb[(wk + p * 16 + lrow) * LDB + h * 16 + lcol]);
                ldmx4(bl[p][h], &Blb[(wk + p * 16 + lrow) * LDB + h * 16 + lcol]);
            }
        #pragma unroll
        for (int p = 0; p < 2; ++p)
            #pragma unroll
            for (int t = 0; t < 2; ++t) {
                float* d = acc[p * 2 + t];
                #pragma unroll
                for (int h = 0; h < 2; ++h) {
                    mma_bf16(d, ah[h],  bh[p][h][t], bh[p][h][t + 2]);
                    mma_bf16(d, ah[h],  bl[p][h][t], bl[p][h][t + 2]);
                    mma_bf16(d, al2[h], bh[p][h][t], bh[p][h][t + 2]);
                }
            }

        if ((it & 7) == 7) {
            // write 16x32 warp score tile for chunk kc, reset acc
            #pragma unroll
            for (int ni = 0; ni < 4; ++ni) {
                const int c = kc * 64 + wk + ni * 8 + (lane & 3) * 2;
                #pragma unroll
                for (int hh = 0; hh < 2; ++hh) {
                    const int row = wq + (lane >> 2) + hh * 8;
                    float2 v;
                    v.x = acc[ni][hh * 2 + 0] * 0.0625f;
                    v.y = acc[ni][hh * 2 + 1] * 0.0625f;
                    *(float2*)&S[row * LDS + c] = v;
                    acc[ni][hh * 2 + 0] = 0.f;
                    acc[ni][hh * 2 + 1] = 0.f;
                }
            }
        }
        __syncthreads();   // guard ring-buffer reuse by next prefetch
    }

    // ---- masked softmax over S rows, write output ----
    const bool is64 = counts_are_64bit(nr_own);
    const int fl = load_count(nr_flags, b, is64);
    const int ou = load_count(nr_own,   b, is64);
    const int en = load_count(nr_enemy, b, is64);

    float* outb = out + (size_t)b * UU * UU + (size_t)row0 * UU;

    #pragma unroll 1
    for (int r8 = 0; r8 < 8; ++r8) {
        const int row = warp * 8 + r8;              // 0..63
        const int grow = row0 + row;
        const bool row_ok = (grow >= fl) && (grow < ou);

        float4 v[4];
        float m = -1e30f;
        #pragma unroll
        for (int j = 0; j < 4; ++j) {
            const int c = lane * 4 + j * 128;
            float4 s = *(const float4*)&S[row * LDS + c];
            #pragma unroll
            for (int e = 0; e < 4; ++e) {
                const bool ok = row_ok && (c + e < en);
                float x = (&s.x)[e];
                (&v[j].x)[e] = ok ? x : x * 1e-9f;
                m = fmaxf(m, (&v[j].x)[e]);
            }
        }
        #pragma unroll
        for (int o = 16; o > 0; o >>= 1)
            m = fmaxf(m, __shfl_xor_sync(0xffffffffu, m, o));

        float sum = 0.f;
        #pragma unroll
        for (int j = 0; j < 4; ++j)
            #pragma unroll
            for (int e = 0; e < 4; ++e) {
                float x = __expf((&v[j].x)[e] - m);
                (&v[j].x)[e] = x;
                sum += x;
            }
        #pragma unroll
        for (int o = 16; o > 0; o >>= 1)
            sum += __shfl_xor_sync(0xffffffffu, sum, o);

        const float inv = 1.0f / sum;
        #pragma unroll
        for (int j = 0; j < 4; ++j) {
            v[j].x *= inv; v[j].y *= inv; v[j].z *= inv; v[j].w *= inv;
            *(float4*)&outb[(size_t)row * UU + lane * 4 + j * 128] = v[j];
        }
    }
}

// ---------------------------------------------------------------------------
extern "C" void kernel_launch(void* const* d_in, const int* in_sizes, int n_in,
                              void* d_out, int out_size)
{
    const float* ar    = (const float*)d_in[0];
    const float* own   = (const float*)d_in[1];
    const float* enemy = (const float*)d_in[2];
    const int* nro     = (const int*)d_in[3];
    const int* nre     = (const int*)d_in[4];
    const int* nrf     = (const int*)d_in[5];
    const float* Wq    = (const float*)d_in[6];
    const float* bq    = (const float*)d_in[7];
    const float* Wk    = (const float*)d_in[8];
    const float* bk    = (const float*)d_in[9];
    float* out = (float*)d_out;

    __nv_bfloat16 *qh, *ql, *kh, *kl;
    cudaGetSymbolAddress((void**)&qh, g_Qhi);
    cudaGetSymbolAddress((void**)&ql, g_Qlo);
    cudaGetSymbolAddress((void**)&kh, g_Khi);
    cudaGetSymbolAddress((void**)&kl, g_Klo);

    cudaFuncSetAttribute(attn_fused, cudaFuncAttributeMaxDynamicSharedMemorySize, SM_TOTAL);

    {   // Q = concat(ar, own) @ Wq + bq
        dim3 grid(AA / BN, MTOT / BM);
        proj_split3<<<grid, 256>>>(ar, AE, AE, own, UE, AE + UE, Wq, bq, qh, ql);
    }
    {   // K = enemy @ Wk + bk
        dim3 grid(AA / BN, MTOT / BM);
        proj_split3<<<grid, 256>>>(enemy, UE, UE, enemy, UE, UE, Wk, bk, kh, kl);
    }
    {   // fused scores + mask + softmax
        dim3 grid(UU / 64, BB);
        attn_fused<<<grid, 256, SM_TOTAL>>>(nro, nre, nrf, out);
    }
}